// round 2
// baseline (speedup 1.0000x reference)
#include <cuda_runtime.h>
#include <math.h>

// Problem sizes (fixed)
#define BB   1024   // batch
#define SS   64     // clips
#define RR   1024   // rnn size
#define HH   512    // att hid size
#define CD   1024   // clip context dim

// ---------------- scratch (no allocation allowed) ----------------
__device__ float g_gates[BB * 4 * RR];      // 16 MB, reused by both LSTMs
__device__ float g_atth [BB * HH];          // 2 MB
__device__ float g_scores[BB * SS];         // 256 KB
__device__ float g_attout[BB * CD];         // 4 MB

// ---------------- tiny init kernels ----------------
__global__ void init_atth_kernel(const float* __restrict__ b_h2a) {
    int idx = blockIdx.x * blockDim.x + threadIdx.x;   // 0 .. 512K-1
    if (idx < BB * HH) g_atth[idx] = b_h2a[idx & (HH - 1)];
}

__global__ void init_scores_kernel(const float* __restrict__ b_alpha) {
    int idx = blockIdx.x * blockDim.x + threadIdx.x;   // 0 .. 65535
    if (idx < BB * SS) g_scores[idx] = b_alpha[0];
}

// ======================================================================
// GEMM 1: gates = [xt | x2 | h] @ [W_ih | W_hh]^T + b_ih + b_hh
// M=1024, N=4096, K=3072 (3 x 1024 segments).  BM=BN=128, BK=16, 256 thr.
// ======================================================================
__global__ __launch_bounds__(256) void gemm_gates_kernel(
    const float* __restrict__ xt, const float* __restrict__ x2in,
    const float* __restrict__ h,
    const float* __restrict__ Wih, const float* __restrict__ Whh,
    const float* __restrict__ bih, const float* __restrict__ bhh,
    int use_attout)
{
    __shared__ __align__(16) float As[16][132];
    __shared__ __align__(16) float Ws[16][132];

    const float* x2 = use_attout ? g_attout : x2in;

    const int tid = threadIdx.x;
    const int tx = tid & 15, ty = tid >> 4;
    const int m0 = blockIdx.y * 128, n0 = blockIdx.x * 128;

    float acc[8][8];
#pragma unroll
    for (int i = 0; i < 8; i++)
#pragma unroll
        for (int j = 0; j < 8; j++) acc[i][j] = 0.f;

    for (int k0 = 0; k0 < 3072; k0 += 16) {
        const float* Aseg; int ka;
        if (k0 < 1024)      { Aseg = xt; ka = k0; }
        else if (k0 < 2048) { Aseg = x2; ka = k0 - 1024; }
        else                { Aseg = h;  ka = k0 - 2048; }
        const float* Wseg; int kw, ldw;
        if (k0 < 2048) { Wseg = Wih; kw = k0;        ldw = 2048; }
        else           { Wseg = Whh; kw = k0 - 2048; ldw = 1024; }

#pragma unroll
        for (int i = 0; i < 2; i++) {
            int lin = tid + i * 256;            // 0..511
            int row = lin >> 2, k4 = (lin & 3) << 2;
            float4 va = *(const float4*)&Aseg[(size_t)(m0 + row) * 1024 + ka + k4];
            As[k4 + 0][row] = va.x; As[k4 + 1][row] = va.y;
            As[k4 + 2][row] = va.z; As[k4 + 3][row] = va.w;
            float4 vw = *(const float4*)&Wseg[(size_t)(n0 + row) * ldw + kw + k4];
            Ws[k4 + 0][row] = vw.x; Ws[k4 + 1][row] = vw.y;
            Ws[k4 + 2][row] = vw.z; Ws[k4 + 3][row] = vw.w;
        }
        __syncthreads();

#pragma unroll
        for (int kk = 0; kk < 16; kk++) {
            float4 a0 = *(const float4*)&As[kk][4 * ty];
            float4 a1 = *(const float4*)&As[kk][64 + 4 * ty];
            float4 b0 = *(const float4*)&Ws[kk][4 * tx];
            float4 b1 = *(const float4*)&Ws[kk][64 + 4 * tx];
            float a[8] = {a0.x, a0.y, a0.z, a0.w, a1.x, a1.y, a1.z, a1.w};
            float b[8] = {b0.x, b0.y, b0.z, b0.w, b1.x, b1.y, b1.z, b1.w};
#pragma unroll
            for (int i = 0; i < 8; i++)
#pragma unroll
                for (int j = 0; j < 8; j++)
                    acc[i][j] = fmaf(a[i], b[j], acc[i][j]);
        }
        __syncthreads();
    }

#pragma unroll
    for (int i = 0; i < 8; i++) {
        int r = (i < 4) ? (4 * ty + i) : (64 + 4 * ty + i - 4);
#pragma unroll
        for (int j = 0; j < 8; j++) {
            int c = (j < 4) ? (4 * tx + j) : (64 + 4 * tx + j - 4);
            int gn = n0 + c;
            g_gates[(size_t)(m0 + r) * 4096 + gn] = acc[i][j] + bih[gn] + bhh[gn];
        }
    }
}

// ======================================================================
// GEMM 2: att_h += pre_h1 @ W_h2a^T   (split-K=4, atomic combine)
// M=1024, N=512, K=1024.
// ======================================================================
__global__ __launch_bounds__(256) void gemm_atth_kernel(
    const float* __restrict__ h1, const float* __restrict__ Wh2a)
{
    __shared__ __align__(16) float As[16][132];
    __shared__ __align__(16) float Ws[16][132];

    const int tid = threadIdx.x;
    const int tx = tid & 15, ty = tid >> 4;
    const int m0 = blockIdx.y * 128, n0 = blockIdx.x * 128;
    const int kbeg = blockIdx.z * 256, kend = kbeg + 256;

    float acc[8][8];
#pragma unroll
    for (int i = 0; i < 8; i++)
#pragma unroll
        for (int j = 0; j < 8; j++) acc[i][j] = 0.f;

    for (int k0 = kbeg; k0 < kend; k0 += 16) {
#pragma unroll
        for (int i = 0; i < 2; i++) {
            int lin = tid + i * 256;
            int row = lin >> 2, k4 = (lin & 3) << 2;
            float4 va = *(const float4*)&h1[(size_t)(m0 + row) * 1024 + k0 + k4];
            As[k4 + 0][row] = va.x; As[k4 + 1][row] = va.y;
            As[k4 + 2][row] = va.z; As[k4 + 3][row] = va.w;
            float4 vw = *(const float4*)&Wh2a[(size_t)(n0 + row) * 1024 + k0 + k4];
            Ws[k4 + 0][row] = vw.x; Ws[k4 + 1][row] = vw.y;
            Ws[k4 + 2][row] = vw.z; Ws[k4 + 3][row] = vw.w;
        }
        __syncthreads();
#pragma unroll
        for (int kk = 0; kk < 16; kk++) {
            float4 a0 = *(const float4*)&As[kk][4 * ty];
            float4 a1 = *(const float4*)&As[kk][64 + 4 * ty];
            float4 b0 = *(const float4*)&Ws[kk][4 * tx];
            float4 b1 = *(const float4*)&Ws[kk][64 + 4 * tx];
            float a[8] = {a0.x, a0.y, a0.z, a0.w, a1.x, a1.y, a1.z, a1.w};
            float b[8] = {b0.x, b0.y, b0.z, b0.w, b1.x, b1.y, b1.z, b1.w};
#pragma unroll
            for (int i = 0; i < 8; i++)
#pragma unroll
                for (int j = 0; j < 8; j++)
                    acc[i][j] = fmaf(a[i], b[j], acc[i][j]);
        }
        __syncthreads();
    }

#pragma unroll
    for (int i = 0; i < 8; i++) {
        int r = (i < 4) ? (4 * ty + i) : (64 + 4 * ty + i - 4);
#pragma unroll
        for (int j = 0; j < 8; j++) {
            int c = (j < 4) ? (4 * tx + j) : (64 + 4 * tx + j - 4);
            atomicAdd(&g_atth[(size_t)(m0 + r) * 512 + n0 + c], acc[i][j]);
        }
    }
}

// ======================================================================
// GEMM 3 (fused): scores[b,s] += sum_n W_alpha[n]*tanh(clip@W_ctx^T + b_ctx + att_h[b])
// M=65536 (rows = b*64+s), N=512, K=1024.
// ======================================================================
__global__ __launch_bounds__(256) void gemm_scores_kernel(
    const float* __restrict__ clip, const float* __restrict__ Wctx,
    const float* __restrict__ bctx, const float* __restrict__ Walpha)
{
    __shared__ __align__(16) float As[16][132];
    __shared__ __align__(16) float Ws[16][132];
    __shared__ float Red[128][17];

    const int tid = threadIdx.x;
    const int tx = tid & 15, ty = tid >> 4;
    const int m0 = blockIdx.y * 128, n0 = blockIdx.x * 128;

    float acc[8][8];
#pragma unroll
    for (int i = 0; i < 8; i++)
#pragma unroll
        for (int j = 0; j < 8; j++) acc[i][j] = 0.f;

    for (int k0 = 0; k0 < 1024; k0 += 16) {
#pragma unroll
        for (int i = 0; i < 2; i++) {
            int lin = tid + i * 256;
            int row = lin >> 2, k4 = (lin & 3) << 2;
            float4 va = *(const float4*)&clip[(size_t)(m0 + row) * 1024 + k0 + k4];
            As[k4 + 0][row] = va.x; As[k4 + 1][row] = va.y;
            As[k4 + 2][row] = va.z; As[k4 + 3][row] = va.w;
            float4 vw = *(const float4*)&Wctx[(size_t)(n0 + row) * 1024 + k0 + k4];
            Ws[k4 + 0][row] = vw.x; Ws[k4 + 1][row] = vw.y;
            Ws[k4 + 2][row] = vw.z; Ws[k4 + 3][row] = vw.w;
        }
        __syncthreads();
#pragma unroll
        for (int kk = 0; kk < 16; kk++) {
            float4 a0 = *(const float4*)&As[kk][4 * ty];
            float4 a1 = *(const float4*)&As[kk][64 + 4 * ty];
            float4 b0 = *(const float4*)&Ws[kk][4 * tx];
            float4 b1 = *(const float4*)&Ws[kk][64 + 4 * tx];
            float a[8] = {a0.x, a0.y, a0.z, a0.w, a1.x, a1.y, a1.z, a1.w};
            float b[8] = {b0.x, b0.y, b0.z, b0.w, b1.x, b1.y, b1.z, b1.w};
#pragma unroll
            for (int i = 0; i < 8; i++)
#pragma unroll
                for (int j = 0; j < 8; j++)
                    acc[i][j] = fmaf(a[i], b[j], acc[i][j]);
        }
        __syncthreads();
    }

    // epilogue: tanh + dot with W_alpha along n, reduce over block columns
    float rsum[8];
#pragma unroll
    for (int i = 0; i < 8; i++) rsum[i] = 0.f;
#pragma unroll
    for (int i = 0; i < 8; i++) {
        int r  = (i < 4) ? (4 * ty + i) : (64 + 4 * ty + i - 4);
        int gm = m0 + r;
        int bb = gm >> 6;
#pragma unroll
        for (int j = 0; j < 8; j++) {
            int c  = (j < 4) ? (4 * tx + j) : (64 + 4 * tx + j - 4);
            int gn = n0 + c;
            float t = tanhf(acc[i][j] + bctx[gn] + g_atth[(size_t)bb * 512 + gn]);
            rsum[i] += t * Walpha[gn];
        }
    }
#pragma unroll
    for (int i = 0; i < 8; i++) {
        int r = (i < 4) ? (4 * ty + i) : (64 + 4 * ty + i - 4);
        Red[r][tx] = rsum[i];
    }
    __syncthreads();
    if (tid < 128) {
        float s = 0.f;
#pragma unroll
        for (int t = 0; t < 16; t++) s += Red[tid][t];
        atomicAdd(&g_scores[m0 + tid], s);
    }
}

// ======================================================================
// softmax over S=64 (mask + renorm) + weighted sum of clip -> att_out
// one block per batch row
// ======================================================================
__global__ __launch_bounds__(256) void softmax_attout_kernel(
    const float* __restrict__ clip, const int* __restrict__ mask)
{
    const int b = blockIdx.x;
    const int tid = threadIdx.x;
    __shared__ float w[64];
    __shared__ float stat;

    if (tid < 64) w[tid] = g_scores[b * 64 + tid];
    __syncthreads();
    if (tid == 0) {
        float m = w[0];
        for (int s = 1; s < 64; s++) m = fmaxf(m, w[s]);
        stat = m;
    }
    __syncthreads();
    if (tid < 64) w[tid] = expf(w[tid] - stat);
    __syncthreads();
    if (tid == 0) {
        float s = 0.f;
        for (int i = 0; i < 64; i++) s += w[i];
        stat = s;
    }
    __syncthreads();
    if (tid < 64) w[tid] = (w[tid] / stat) * (float)mask[b * 64 + tid];
    __syncthreads();
    if (tid == 0) {
        float s = 0.f;
        for (int i = 0; i < 64; i++) s += w[i];
        stat = s;
    }
    __syncthreads();
    if (tid < 64) w[tid] = w[tid] / stat;
    __syncthreads();

#pragma unroll
    for (int d = tid; d < 1024; d += 256) {
        float acc = 0.f;
#pragma unroll 8
        for (int s = 0; s < 64; s++)
            acc += w[s] * clip[((size_t)b * 64 + s) * 1024 + d];
        g_attout[(size_t)b * 1024 + d] = acc;
    }
}

// ======================================================================
// LSTM pointwise: gates -> h_new, c_new; writes output/new_h/new_c slices
// ======================================================================
__global__ __launch_bounds__(256) void lstm_pointwise_kernel(
    const float* __restrict__ state_c, int stream, float* __restrict__ out)
{
    int idx = blockIdx.x * blockDim.x + threadIdx.x;   // 0..1M-1
    int b = idx >> 10, j = idx & 1023;
    const float* g = g_gates + (size_t)b * 4096;
    float ig = 1.f / (1.f + expf(-g[j]));
    float fg = 1.f / (1.f + expf(-g[1024 + j]));
    float gg = tanhf(g[2048 + j]);
    float og = 1.f / (1.f + expf(-g[3072 + j]));
    float c_old = state_c[(size_t)stream * 1048576 + idx];
    float c_new = fg * c_old + ig * gg;
    float h_new = og * tanhf(c_new);
    out[(size_t)b * 2048 + stream * 1024 + j] = h_new;                 // output
    out[2097152 + (size_t)stream * 1048576 + idx] = h_new;             // new_h
    out[4194304 + (size_t)stream * 1048576 + idx] = c_new;             // new_c
}

// ======================================================================
extern "C" void kernel_launch(void* const* d_in, const int* in_sizes, int n_in,
                              void* d_out, int out_size)
{
    const float* xt       = (const float*)d_in[0];
    // d_in[1] = video (unused)
    const float* event    = (const float*)d_in[2];
    const float* clip     = (const float*)d_in[3];
    const int*   clipmask = (const int*)  d_in[4];
    const float* state_h  = (const float*)d_in[5];
    const float* state_c  = (const float*)d_in[6];
    const float* W_ih0    = (const float*)d_in[7];
    const float* b_ih0    = (const float*)d_in[8];
    const float* W_hh0    = (const float*)d_in[9];
    const float* b_hh0    = (const float*)d_in[10];
    const float* W_ih1    = (const float*)d_in[11];
    const float* b_ih1    = (const float*)d_in[12];
    const float* W_hh1    = (const float*)d_in[13];
    const float* b_hh1    = (const float*)d_in[14];
    const float* W_ctx    = (const float*)d_in[15];
    const float* b_ctx    = (const float*)d_in[16];
    const float* W_h2a    = (const float*)d_in[17];
    const float* b_h2a    = (const float*)d_in[18];
    const float* W_alpha  = (const float*)d_in[19];
    const float* b_alpha  = (const float*)d_in[20];
    float* out = (float*)d_out;

    const float* h0 = state_h;              // state_h[0]
    const float* h1 = state_h + 1048576;    // state_h[1] (pre_h1)

    // attention pre-work
    init_atth_kernel<<<2048, 256>>>(b_h2a);
    init_scores_kernel<<<256, 256>>>(b_alpha);
    gemm_atth_kernel<<<dim3(4, 8, 4), 256>>>(h1, W_h2a);

    // stream 0 LSTM
    gemm_gates_kernel<<<dim3(32, 8), 256>>>(xt, event, h0, W_ih0, W_hh0,
                                            b_ih0, b_hh0, 0);
    lstm_pointwise_kernel<<<4096, 256>>>(state_c, 0, out);

    // attention scores + softmax + context
    gemm_scores_kernel<<<dim3(4, 512), 256>>>(clip, W_ctx, b_ctx, W_alpha);
    softmax_attout_kernel<<<1024, 256>>>(clip, clipmask);

    // stream 1 LSTM (x2 = g_attout, selected via flag)
    gemm_gates_kernel<<<dim3(32, 8), 256>>>(xt, nullptr, h1, W_ih1, W_hh1,
                                            b_ih1, b_hh1, 1);
    lstm_pointwise_kernel<<<4096, 256>>>(state_c, 1, out);
}

// round 7
// speedup vs baseline: 1.8563x; 1.8563x over previous
#include <cuda_runtime.h>
#include <cstdint>
#include <math.h>

// ---------------- scratch (no allocation allowed) ----------------
__device__ float g_gates[1024 * 4096];     // 16 MB, reused by both LSTMs
__device__ float g_atth [1024 * 512];      // 2 MB
__device__ float g_scores[1024 * 64];      // 256 KB
__device__ float g_attout[1024 * 1024];    // 4 MB

// ================= helpers =================
__device__ __forceinline__ uint32_t smem_u32(const void* p) {
    uint32_t a;
    asm("{ .reg .u64 t; cvta.to.shared.u64 t, %1; cvt.u32.u64 %0, t; }"
        : "=r"(a) : "l"(p));
    return a;
}

#define CP_ASYNC16(dst, src) \
    asm volatile("cp.async.cg.shared.global [%0], [%1], 16;" \
                 :: "r"(dst), "l"(src))
#define CP_COMMIT() asm volatile("cp.async.commit_group;")
#define CP_WAIT1()  asm volatile("cp.async.wait_group 1;")
#define CP_WAIT0()  asm volatile("cp.async.wait_group 0;")

__device__ __forceinline__ void mma8(float* c, const uint32_t* a, const uint32_t* b) {
    asm volatile(
        "mma.sync.aligned.m16n8k8.row.col.f32.tf32.tf32.f32 "
        "{%0,%1,%2,%3}, {%4,%5,%6,%7}, {%8,%9}, {%0,%1,%2,%3};"
        : "+f"(c[0]), "+f"(c[1]), "+f"(c[2]), "+f"(c[3])
        : "r"(a[0]), "r"(a[1]), "r"(a[2]), "r"(a[3]), "r"(b[0]), "r"(b[1]));
}

__device__ __forceinline__ uint32_t tf32_rna(float x) {
    uint32_t u;
    asm("cvt.rna.tf32.f32 %0, %1;" : "=r"(u) : "f"(x));
    return u;
}

// split into (hi, lo) tf32 pair: hi = truncate-to-tf32(x), lo = tf32(x - hi)
__device__ __forceinline__ void split_tf32(float x, uint32_t& hi, uint32_t& lo) {
    uint32_t xb = __float_as_uint(x);
    hi = xb & 0xFFFFE000u;
    float l = x - __uint_as_float(hi);
    lo = __float_as_uint(l) & 0xFFFFE000u;
}

// ================= tiny init kernels =================
__global__ void init_atth_kernel(const float* __restrict__ b_h2a) {
    int idx = blockIdx.x * blockDim.x + threadIdx.x;
    if (idx < 1024 * 512) g_atth[idx] = b_h2a[idx & 511];
}
__global__ void init_scores_kernel(const float* __restrict__ b_alpha) {
    int idx = blockIdx.x * blockDim.x + threadIdx.x;
    if (idx < 1024 * 64) g_scores[idx] = b_alpha[0];
}

// ======================================================================
// tf32 mma.sync GEMM:  C[M,N] = A[M,K] @ W[N,K]^T
// BM=128, BN=256, BK=32, 512 threads (16 warps 4m x 4n), warp tile 32x64.
// NPASS=3 -> 3xTF32 (near-fp32); NPASS=1 -> plain tf32 (rna).
// MODE=0: gates epilogue -> writes g_gates (device symbol) directly
// MODE=1: scores epilogue (sum_n e1[n]*tanh(D + e0[n] + g_atth[b,n]) -> atomic g_scores)
// A = segments [A0 | A1 | A2] each 1024 wide (ld 1024); A1 -> g_attout if use_attout.
// B = [B01 rows (k<2048, ld=ldB01) | B2 (ld=1024)].
// ======================================================================
template<int NPASS, int MODE>
__global__ void __launch_bounds__(512) mma_gemm_kernel(
    const float* __restrict__ A0, const float* __restrict__ A1,
    const float* __restrict__ A2,
    const float* __restrict__ B01, int ldB01, const float* __restrict__ B2,
    int K, int use_attout,
    const float* __restrict__ e0, const float* __restrict__ e1)
{
    constexpr int BM = 128, BN = 256, BK = 32, PITCH = 36;
    constexpr int AF = BM * PITCH;          // floats per A stage (4608)
    constexpr int BF = BN * PITCH;          // floats per B stage (9216)
    constexpr int STGF = AF + BF;           // 13824 floats = 55296 B

    extern __shared__ float smf[];
    const uint32_t smu = smem_u32(smf);

    const int tid = threadIdx.x;
    const int lane = tid & 31, w = tid >> 5;
    const int wm = w & 3, wn = w >> 2;            // 4 x 4 warps
    const int g = lane >> 2, tig = lane & 3;
    const int m0 = blockIdx.y * BM, n0 = blockIdx.x * BN;
    const float* A1r = use_attout ? g_attout : A1;

    float acc[2][8][4];
#pragma unroll
    for (int mt = 0; mt < 2; mt++)
#pragma unroll
        for (int nt = 0; nt < 8; nt++)
#pragma unroll
            for (int r = 0; r < 4; r++) acc[mt][nt][r] = 0.f;

    const int T = K / BK;

    // ---- prefetch helper (t = k-iter, buf = stage) ----
    auto prefetch = [&](int t, int buf) {
        const int k0 = t * BK;
        const float* Aseg; int ka;
        if (k0 < 1024)      { Aseg = A0;  ka = k0; }
        else if (k0 < 2048) { Aseg = A1r; ka = k0 - 1024; }
        else                { Aseg = A2;  ka = k0 - 2048; }
        const float* Bseg; int kb, ldb;
        if (k0 < 2048) { Bseg = B01; kb = k0;        ldb = ldB01; }
        else           { Bseg = B2;  kb = k0 - 2048; ldb = 1024; }
        const uint32_t abase = smu + (uint32_t)buf * STGF * 4;
        const uint32_t bbase = abase + AF * 4;
#pragma unroll
        for (int i = 0; i < 2; i++) {               // A: 1024 f4 / 512 thr
            int q = tid + i * 512;
            int row = q >> 3, c4 = q & 7;
            CP_ASYNC16(abase + (uint32_t)(row * PITCH + c4 * 4) * 4,
                       (const void*)&Aseg[(size_t)(m0 + row) * 1024 + ka + c4 * 4]);
        }
#pragma unroll
        for (int i = 0; i < 4; i++) {               // B: 2048 f4 / 512 thr
            int q = tid + i * 512;
            int row = q >> 3, c4 = q & 7;
            CP_ASYNC16(bbase + (uint32_t)(row * PITCH + c4 * 4) * 4,
                       (const void*)&Bseg[(size_t)(n0 + row) * ldb + kb + c4 * 4]);
        }
        CP_COMMIT();
    };

    prefetch(0, 0);

    for (int t = 0; t < T; t++) {
        const int buf = t & 1;
        if (t + 1 < T) { prefetch(t + 1, buf ^ 1); CP_WAIT1(); }
        else           { CP_WAIT0(); }
        __syncthreads();

        const float* As = smf + buf * STGF;
        const float* Bs = As + AF;

#pragma unroll
        for (int s = 0; s < 4; s++) {
            // A fragments for this k-step (2 m-tiles)
            uint32_t ah[2][4], al[2][4];
#pragma unroll
            for (int mt = 0; mt < 2; mt++) {
                const float* ap = As + (wm * 32 + mt * 16 + g) * PITCH + s * 8 + tig;
                float x0 = ap[0], x1 = ap[8 * PITCH], x2 = ap[4], x3 = ap[8 * PITCH + 4];
                if (NPASS == 3) {
                    split_tf32(x0, ah[mt][0], al[mt][0]);
                    split_tf32(x1, ah[mt][1], al[mt][1]);
                    split_tf32(x2, ah[mt][2], al[mt][2]);
                    split_tf32(x3, ah[mt][3], al[mt][3]);
                } else {
                    ah[mt][0] = tf32_rna(x0); ah[mt][1] = tf32_rna(x1);
                    ah[mt][2] = tf32_rna(x2); ah[mt][3] = tf32_rna(x3);
                }
            }
            // B fragments one n-tile at a time (keeps regs low)
#pragma unroll
            for (int nt = 0; nt < 8; nt++) {
                const float* bp = Bs + (wn * 64 + nt * 8 + g) * PITCH + s * 8 + tig;
                float y0 = bp[0], y1 = bp[4];
                uint32_t bh[2], bl[2];
                if (NPASS == 3) {
                    split_tf32(y0, bh[0], bl[0]);
                    split_tf32(y1, bh[1], bl[1]);
                } else {
                    bh[0] = tf32_rna(y0); bh[1] = tf32_rna(y1);
                }
#pragma unroll
                for (int mt = 0; mt < 2; mt++) {
                    mma8(acc[mt][nt], ah[mt], bh);
                    if (NPASS == 3) {
                        mma8(acc[mt][nt], ah[mt], bl);
                        mma8(acc[mt][nt], al[mt], bh);
                    }
                }
            }
        }
        __syncthreads();
    }

    // ---------------- epilogue ----------------
    if (MODE == 0) {
#pragma unroll
        for (int mt = 0; mt < 2; mt++) {
            const int r0 = m0 + wm * 32 + mt * 16 + g;
            const int r1 = r0 + 8;
#pragma unroll
            for (int nt = 0; nt < 8; nt++) {
                const int cb = n0 + wn * 64 + nt * 8 + tig * 2;
                float2 bA = *(const float2*)&e0[cb];
                float2 bB = *(const float2*)&e1[cb];
                const float* a = acc[mt][nt];
                float2 v0 = { a[0] + bA.x + bB.x, a[1] + bA.y + bB.y };
                float2 v1 = { a[2] + bA.x + bB.x, a[3] + bA.y + bB.y };
                // device-side symbol reference (NOT a host-passed pointer)
                *(float2*)&g_gates[(size_t)r0 * 4096 + cb] = v0;
                *(float2*)&g_gates[(size_t)r1 * 4096 + cb] = v1;
            }
        }
    } else {
#pragma unroll
        for (int mt = 0; mt < 2; mt++) {
            const int r0 = m0 + wm * 32 + mt * 16 + g;
            const int r1 = r0 + 8;
            const int bb0 = r0 >> 6, bb1 = r1 >> 6;
            float s0 = 0.f, s1 = 0.f;
#pragma unroll
            for (int nt = 0; nt < 8; nt++) {
                const int cb = n0 + wn * 64 + nt * 8 + tig * 2;   // 0..511
                float2 bc = *(const float2*)&e0[cb];
                float2 wa = *(const float2*)&e1[cb];
                float2 a0 = *(const float2*)&g_atth[(size_t)bb0 * 512 + cb];
                float2 a1 = *(const float2*)&g_atth[(size_t)bb1 * 512 + cb];
                const float* a = acc[mt][nt];
                s0 += tanhf(a[0] + bc.x + a0.x) * wa.x
                    + tanhf(a[1] + bc.y + a0.y) * wa.y;
                s1 += tanhf(a[2] + bc.x + a1.x) * wa.x
                    + tanhf(a[3] + bc.y + a1.y) * wa.y;
            }
            // reduce over the 4 lanes of the quad (same rows)
            s0 += __shfl_xor_sync(0xffffffffu, s0, 1);
            s0 += __shfl_xor_sync(0xffffffffu, s0, 2);
            s1 += __shfl_xor_sync(0xffffffffu, s1, 1);
            s1 += __shfl_xor_sync(0xffffffffu, s1, 2);
            if (tig == 0) {
                atomicAdd(&g_scores[r0], s0);
                atomicAdd(&g_scores[r1], s1);
            }
        }
    }
}

// ======================================================================
// GEMM (small, SIMT): att_h += pre_h1 @ W_h2a^T  (split-K=4)
// ======================================================================
__global__ __launch_bounds__(256) void gemm_atth_kernel(
    const float* __restrict__ h1, const float* __restrict__ Wh2a)
{
    __shared__ __align__(16) float As[16][132];
    __shared__ __align__(16) float Ws[16][132];
    const int tid = threadIdx.x;
    const int tx = tid & 15, ty = tid >> 4;
    const int m0 = blockIdx.y * 128, n0 = blockIdx.x * 128;
    const int kbeg = blockIdx.z * 256, kend = kbeg + 256;

    float acc[8][8];
#pragma unroll
    for (int i = 0; i < 8; i++)
#pragma unroll
        for (int j = 0; j < 8; j++) acc[i][j] = 0.f;

    for (int k0 = kbeg; k0 < kend; k0 += 16) {
#pragma unroll
        for (int i = 0; i < 2; i++) {
            int lin = tid + i * 256;
            int row = lin >> 2, k4 = (lin & 3) << 2;
            float4 va = *(const float4*)&h1[(size_t)(m0 + row) * 1024 + k0 + k4];
            As[k4 + 0][row] = va.x; As[k4 + 1][row] = va.y;
            As[k4 + 2][row] = va.z; As[k4 + 3][row] = va.w;
            float4 vw = *(const float4*)&Wh2a[(size_t)(n0 + row) * 1024 + k0 + k4];
            Ws[k4 + 0][row] = vw.x; Ws[k4 + 1][row] = vw.y;
            Ws[k4 + 2][row] = vw.z; Ws[k4 + 3][row] = vw.w;
        }
        __syncthreads();
#pragma unroll
        for (int kk = 0; kk < 16; kk++) {
            float4 a0 = *(const float4*)&As[kk][4 * ty];
            float4 a1 = *(const float4*)&As[kk][64 + 4 * ty];
            float4 b0 = *(const float4*)&Ws[kk][4 * tx];
            float4 b1 = *(const float4*)&Ws[kk][64 + 4 * tx];
            float a[8] = {a0.x, a0.y, a0.z, a0.w, a1.x, a1.y, a1.z, a1.w};
            float b[8] = {b0.x, b0.y, b0.z, b0.w, b1.x, b1.y, b1.z, b1.w};
#pragma unroll
            for (int i = 0; i < 8; i++)
#pragma unroll
                for (int j = 0; j < 8; j++)
                    acc[i][j] = fmaf(a[i], b[j], acc[i][j]);
        }
        __syncthreads();
    }
#pragma unroll
    for (int i = 0; i < 8; i++) {
        int r = (i < 4) ? (4 * ty + i) : (64 + 4 * ty + i - 4);
#pragma unroll
        for (int j = 0; j < 8; j++) {
            int c = (j < 4) ? (4 * tx + j) : (64 + 4 * tx + j - 4);
            atomicAdd(&g_atth[(size_t)(m0 + r) * 512 + n0 + c], acc[i][j]);
        }
    }
}

// ======================================================================
// softmax over S=64 (mask + renorm) + weighted sum of clip -> g_attout
// ======================================================================
__global__ __launch_bounds__(256) void softmax_attout_kernel(
    const float* __restrict__ clip, const int* __restrict__ mask)
{
    const int b = blockIdx.x;
    const int tid = threadIdx.x;
    __shared__ float w[64];
    __shared__ float stat;

    if (tid < 64) w[tid] = g_scores[b * 64 + tid];
    __syncthreads();
    if (tid == 0) {
        float m = w[0];
        for (int s = 1; s < 64; s++) m = fmaxf(m, w[s]);
        stat = m;
    }
    __syncthreads();
    if (tid < 64) w[tid] = expf(w[tid] - stat);
    __syncthreads();
    if (tid == 0) {
        float s = 0.f;
        for (int i = 0; i < 64; i++) s += w[i];
        stat = s;
    }
    __syncthreads();
    if (tid < 64) w[tid] = (w[tid] / stat) * (float)mask[b * 64 + tid];
    __syncthreads();
    if (tid == 0) {
        float s = 0.f;
        for (int i = 0; i < 64; i++) s += w[i];
        stat = s;
    }
    __syncthreads();
    if (tid < 64) w[tid] = w[tid] / stat;
    __syncthreads();

    for (int d = tid; d < 1024; d += 256) {
        float acc = 0.f;
#pragma unroll 8
        for (int s = 0; s < 64; s++)
            acc += w[s] * clip[((size_t)b * 64 + s) * 1024 + d];
        g_attout[(size_t)b * 1024 + d] = acc;
    }
}

// ======================================================================
// LSTM pointwise
// ======================================================================
__global__ __launch_bounds__(256) void lstm_pointwise_kernel(
    const float* __restrict__ state_c, int stream, float* __restrict__ out)
{
    int idx = blockIdx.x * blockDim.x + threadIdx.x;
    int b = idx >> 10, j = idx & 1023;
    const float* g = g_gates + (size_t)b * 4096;
    float ig = 1.f / (1.f + expf(-g[j]));
    float fg = 1.f / (1.f + expf(-g[1024 + j]));
    float gg = tanhf(g[2048 + j]);
    float og = 1.f / (1.f + expf(-g[3072 + j]));
    float c_old = state_c[(size_t)stream * 1048576 + idx];
    float c_new = fg * c_old + ig * gg;
    float h_new = og * tanhf(c_new);
    out[(size_t)b * 2048 + stream * 1024 + j] = h_new;
    out[2097152 + (size_t)stream * 1048576 + idx] = h_new;
    out[4194304 + (size_t)stream * 1048576 + idx] = c_new;
}

// ======================================================================
extern "C" void kernel_launch(void* const* d_in, const int* in_sizes, int n_in,
                              void* d_out, int out_size)
{
    const float* xt       = (const float*)d_in[0];
    const float* event    = (const float*)d_in[2];
    const float* clip     = (const float*)d_in[3];
    const int*   clipmask = (const int*)  d_in[4];
    const float* state_h  = (const float*)d_in[5];
    const float* state_c  = (const float*)d_in[6];
    const float* W_ih0    = (const float*)d_in[7];
    const float* b_ih0    = (const float*)d_in[8];
    const float* W_hh0    = (const float*)d_in[9];
    const float* b_hh0    = (const float*)d_in[10];
    const float* W_ih1    = (const float*)d_in[11];
    const float* b_ih1    = (const float*)d_in[12];
    const float* W_hh1    = (const float*)d_in[13];
    const float* b_hh1    = (const float*)d_in[14];
    const float* W_ctx    = (const float*)d_in[15];
    const float* b_ctx    = (const float*)d_in[16];
    const float* W_h2a    = (const float*)d_in[17];
    const float* b_h2a    = (const float*)d_in[18];
    const float* W_alpha  = (const float*)d_in[19];
    const float* b_alpha  = (const float*)d_in[20];
    float* out = (float*)d_out;

    const float* h0 = state_h;
    const float* h1 = state_h + 1048576;

    const int SMEM = 2 * 55296;   // 110592 B dynamic smem
    cudaFuncSetAttribute(mma_gemm_kernel<3, 0>,
                         cudaFuncAttributeMaxDynamicSharedMemorySize, SMEM);
    cudaFuncSetAttribute(mma_gemm_kernel<1, 1>,
                         cudaFuncAttributeMaxDynamicSharedMemorySize, SMEM);

    // attention pre-work
    init_atth_kernel<<<2048, 256>>>(b_h2a);
    init_scores_kernel<<<256, 256>>>(b_alpha);
    gemm_atth_kernel<<<dim3(4, 8, 4), 256>>>(h1, W_h2a);

    // stream 0 LSTM: gates = [xt|event|h0] @ [W_ih0|W_hh0]^T + biases
    mma_gemm_kernel<3, 0><<<dim3(16, 8), 512, SMEM>>>(
        xt, event, h0, W_ih0, 2048, W_hh0, 3072, 0, b_ih0, b_hh0);
    lstm_pointwise_kernel<<<4096, 256>>>(state_c, 0, out);

    // attention scores: fused clip@W_ctx^T + bias + atth + tanh + W_alpha reduce
    mma_gemm_kernel<1, 1><<<dim3(2, 512), 512, SMEM>>>(
        clip, clip, clip, W_ctx, 1024, W_ctx, 1024, 0, b_ctx, W_alpha);
    softmax_attout_kernel<<<1024, 256>>>(clip, clipmask);

    // stream 1 LSTM: gates = [xt|att|h1] @ [W_ih1|W_hh1]^T + biases
    mma_gemm_kernel<3, 0><<<dim3(16, 8), 512, SMEM>>>(
        xt, nullptr, h1, W_ih1, 2048, W_hh1, 3072, 1, b_ih1, b_hh1);
    lstm_pointwise_kernel<<<4096, 256>>>(state_c, 1, out);
}

// round 10
// speedup vs baseline: 2.3136x; 1.2464x over previous
#include <cuda_runtime.h>
#include <cuda_bf16.h>
#include <cstdint>
#include <math.h>

// ---------------- scratch (no allocation allowed) ----------------
__device__ float g_gates[1024 * 4096];     // 16 MB
__device__ float g_atth [1024 * 512];      // 2 MB
__device__ float g_scores[1024 * 64];      // 256 KB
__device__ float g_attout[1024 * 1024];    // 4 MB

// bf16 hi/lo split operands (weights 4096x3072, activations 1024x3072)
__device__ __nv_bfloat16 g_Whi0[4096 * 3072];
__device__ __nv_bfloat16 g_Wlo0[4096 * 3072];
__device__ __nv_bfloat16 g_Whi1[4096 * 3072];
__device__ __nv_bfloat16 g_Wlo1[4096 * 3072];
__device__ __nv_bfloat16 g_Ahi0[1024 * 3072];
__device__ __nv_bfloat16 g_Alo0[1024 * 3072];
__device__ __nv_bfloat16 g_Ahi1[1024 * 3072];
__device__ __nv_bfloat16 g_Alo1[1024 * 3072];

// ================= helpers =================
__device__ __forceinline__ uint32_t smem_u32(const void* p) {
    uint32_t a;
    asm("{ .reg .u64 t; cvta.to.shared.u64 t, %1; cvt.u32.u64 %0, t; }"
        : "=r"(a) : "l"(p));
    return a;
}

#define CP_ASYNC16(dst, src) \
    asm volatile("cp.async.cg.shared.global [%0], [%1], 16;" \
                 :: "r"(dst), "l"(src))
#define CP_COMMIT() asm volatile("cp.async.commit_group;")
#define CP_WAIT2()  asm volatile("cp.async.wait_group 2;")
#define CP_WAIT1()  asm volatile("cp.async.wait_group 1;")
#define CP_WAIT0()  asm volatile("cp.async.wait_group 0;")

#define LDMX4(r0, r1, r2, r3, addr) \
    asm volatile("ldmatrix.sync.aligned.m8n8.x4.shared.b16 {%0,%1,%2,%3}, [%4];" \
                 : "=r"(r0), "=r"(r1), "=r"(r2), "=r"(r3) : "r"(addr))

__device__ __forceinline__ void mma_bf16(float* c, const uint32_t* a,
                                         uint32_t b0, uint32_t b1) {
    asm volatile(
        "mma.sync.aligned.m16n8k16.row.col.f32.bf16.bf16.f32 "
        "{%0,%1,%2,%3}, {%4,%5,%6,%7}, {%8,%9}, {%0,%1,%2,%3};"
        : "+f"(c[0]), "+f"(c[1]), "+f"(c[2]), "+f"(c[3])
        : "r"(a[0]), "r"(a[1]), "r"(a[2]), "r"(a[3]), "r"(b0), "r"(b1));
}

__device__ __forceinline__ void mma8(float* c, const uint32_t* a, const uint32_t* b) {
    asm volatile(
        "mma.sync.aligned.m16n8k8.row.col.f32.tf32.tf32.f32 "
        "{%0,%1,%2,%3}, {%4,%5,%6,%7}, {%8,%9}, {%0,%1,%2,%3};"
        : "+f"(c[0]), "+f"(c[1]), "+f"(c[2]), "+f"(c[3])
        : "r"(a[0]), "r"(a[1]), "r"(a[2]), "r"(a[3]), "r"(b[0]), "r"(b[1]));
}

__device__ __forceinline__ uint32_t tf32_rna(float x) {
    uint32_t u;
    asm("cvt.rna.tf32.f32 %0, %1;" : "=r"(u) : "f"(x));
    return u;
}

__device__ __forceinline__ void bsplit(float x, __nv_bfloat16& hi, __nv_bfloat16& lo) {
    hi = __float2bfloat16(x);
    lo = __float2bfloat16(x - __bfloat162float(hi));
}

// ================= split (fp32 -> bf16 hi/lo) kernels =================
// weights: dst[n][k] (n<4096, k<3072), k<2048 from Wih (ld 2048), else Whh (ld 1024)
__global__ __launch_bounds__(256) void split_w_kernel(
    const float* __restrict__ Wih, const float* __restrict__ Whh, int which)
{
    __nv_bfloat16* hi = which ? g_Whi1 : g_Whi0;
    __nv_bfloat16* lo = which ? g_Wlo1 : g_Wlo0;
    int q = blockIdx.x * blockDim.x + threadIdx.x;      // float4 index
    if (q >= 4096 * 768) return;
    int row = q / 768, c4 = (q - row * 768) * 4;
    float4 v = (c4 < 2048)
        ? *(const float4*)&Wih[(size_t)row * 2048 + c4]
        : *(const float4*)&Whh[(size_t)row * 1024 + (c4 - 2048)];
    __nv_bfloat16 h[4], l[4];
    bsplit(v.x, h[0], l[0]); bsplit(v.y, h[1], l[1]);
    bsplit(v.z, h[2], l[2]); bsplit(v.w, h[3], l[3]);
    size_t o = (size_t)row * 3072 + c4;
    *(uint2*)&hi[o] = *(uint2*)h;
    *(uint2*)&lo[o] = *(uint2*)l;
}

// activations: src [1024x1024] fp32 (or g_attout) -> A{which} cols [coloff..coloff+1023]
__global__ __launch_bounds__(256) void split_a_kernel(
    const float* __restrict__ src, int use_attout, int which, int coloff)
{
    const float* s = use_attout ? g_attout : src;
    __nv_bfloat16* hi = which ? g_Ahi1 : g_Ahi0;
    __nv_bfloat16* lo = which ? g_Alo1 : g_Alo0;
    int q = blockIdx.x * blockDim.x + threadIdx.x;      // float4 index
    if (q >= 1024 * 256) return;
    int row = q >> 8, c4 = (q & 255) * 4;
    float4 v = *(const float4*)&s[(size_t)row * 1024 + c4];
    __nv_bfloat16 h[4], l[4];
    bsplit(v.x, h[0], l[0]); bsplit(v.y, h[1], l[1]);
    bsplit(v.z, h[2], l[2]); bsplit(v.w, h[3], l[3]);
    size_t o = (size_t)row * 3072 + coloff + c4;
    *(uint2*)&hi[o] = *(uint2*)h;
    *(uint2*)&lo[o] = *(uint2*)l;
}

// ================= tiny init kernels =================
__global__ void init_atth_kernel(const float* __restrict__ b_h2a) {
    int idx = blockIdx.x * blockDim.x + threadIdx.x;
    if (idx < 1024 * 512) g_atth[idx] = b_h2a[idx & 511];
}
__global__ void init_scores_kernel(const float* __restrict__ b_alpha) {
    int idx = blockIdx.x * blockDim.x + threadIdx.x;
    if (idx < 1024 * 64) g_scores[idx] = b_alpha[0];
}

// ======================================================================
// bf16 gates GEMM (3-term via augmented K'=9216):
//   gates = A'[1024,9216] @ W'[4096,9216]^T + b_ih + b_hh -> g_gates
//   A' = [Ahi | Alo | Ahi], W' = [Whi | Whi | Wlo]  (each seg 3072)
// BM=128, BN=256, BK=64 bf16 (128B rows, XOR swizzle), 3-stage cp.async,
// 512 threads (16 warps 4m x 4n), warp tile 32x64, ldmatrix + m16n8k16.
// B smem is n-major (= col-major B); fragments pair along K -> NON-trans ldmatrix.
// ======================================================================
__global__ void __launch_bounds__(512) bf16_gates_kernel(
    int which, const float* __restrict__ e0, const float* __restrict__ e1)
{
    constexpr int ASZ = 128 * 128;          // bytes per A stage (16384)
    constexpr int BSZ = 256 * 128;          // bytes per B stage (32768)
    constexpr int STG = ASZ + BSZ;          // 49152
    constexpr int T = 144;                  // 9216 / 64

    const __nv_bfloat16* Ahi = which ? g_Ahi1 : g_Ahi0;
    const __nv_bfloat16* Alo = which ? g_Alo1 : g_Alo0;
    const __nv_bfloat16* Whi = which ? g_Whi1 : g_Whi0;
    const __nv_bfloat16* Wlo = which ? g_Wlo1 : g_Wlo0;

    extern __shared__ char smc[];
    const uint32_t smu = smem_u32(smc);

    const int tid = threadIdx.x;
    const int lane = tid & 31, w = tid >> 5;
    const int wm = w & 3, wn = w >> 2;
    const int g = lane >> 2, tig = lane & 3;
    const int sub = lane >> 3, sr = lane & 7;
    const int m0 = blockIdx.y * 128, n0 = blockIdx.x * 256;

    float acc[2][8][4];
#pragma unroll
    for (int mt = 0; mt < 2; mt++)
#pragma unroll
        for (int nt = 0; nt < 8; nt++)
#pragma unroll
            for (int r = 0; r < 4; r++) acc[mt][nt][r] = 0.f;

    auto prefetch = [&](int t, int buf) {
        const int seg = t / 48;
        const int kk = t * 64 - seg * 3072;
        const __nv_bfloat16* As = (seg == 1) ? Alo : Ahi;
        const __nv_bfloat16* Bs = (seg == 2) ? Wlo : Whi;
        const uint32_t abase = smu + (uint32_t)buf * STG;
        const uint32_t bbase = abase + ASZ;
#pragma unroll
        for (int i = 0; i < 2; i++) {                 // A: 1024 chunks / 512 thr
            int q = tid + i * 512;
            int row = q >> 3, c = q & 7;
            CP_ASYNC16(abase + row * 128 + ((c ^ (row & 7)) << 4),
                       (const void*)&As[(size_t)(m0 + row) * 3072 + kk + c * 8]);
        }
#pragma unroll
        for (int i = 0; i < 4; i++) {                 // B: 2048 chunks / 512 thr
            int q = tid + i * 512;
            int row = q >> 3, c = q & 7;
            CP_ASYNC16(bbase + row * 128 + ((c ^ (row & 7)) << 4),
                       (const void*)&Bs[(size_t)(n0 + row) * 3072 + kk + c * 8]);
        }
        CP_COMMIT();
    };

    prefetch(0, 0);
    prefetch(1, 1);

    for (int t = 0; t < T; t++) {
        const int buf = t % 3;
        if (t + 2 < T) { prefetch(t + 2, (t + 2) % 3); CP_WAIT2(); }
        else if (t + 1 < T) { CP_WAIT1(); }
        else { CP_WAIT0(); }
        __syncthreads();

        const uint32_t abase = smu + (uint32_t)buf * STG;
        const uint32_t bbase = abase + ASZ;

#pragma unroll
        for (int s = 0; s < 4; s++) {
            uint32_t a[2][4];
#pragma unroll
            for (int mt = 0; mt < 2; mt++) {
                int r = wm * 32 + mt * 16 + (sub & 1) * 8 + sr;
                int ch = 2 * s + (sub >> 1);
                LDMX4(a[mt][0], a[mt][1], a[mt][2], a[mt][3],
                      abase + r * 128 + ((ch ^ (r & 7)) << 4));
            }
#pragma unroll
            for (int ntp = 0; ntp < 4; ntp++) {
                // matrices: 0:(n 0-7,k0-7)=b0 t0, 1:(n 0-7,k8-15)=b1 t0,
                //           2:(n 8-15,k0-7)=b0 t1, 3:(n 8-15,k8-15)=b1 t1
                int r = wn * 64 + ntp * 16 + ((sub >> 1) & 1) * 8 + sr;
                int ch = 2 * s + (sub & 1);
                uint32_t b0, b1, b2, b3;
                LDMX4(b0, b1, b2, b3, bbase + r * 128 + ((ch ^ (r & 7)) << 4));
                mma_bf16(acc[0][2 * ntp],     a[0], b0, b1);
                mma_bf16(acc[1][2 * ntp],     a[1], b0, b1);
                mma_bf16(acc[0][2 * ntp + 1], a[0], b2, b3);
                mma_bf16(acc[1][2 * ntp + 1], a[1], b2, b3);
            }
        }
        __syncthreads();
    }

    // epilogue: gates + biases -> g_gates (device symbol)
#pragma unroll
    for (int mt = 0; mt < 2; mt++) {
        const int r0 = m0 + wm * 32 + mt * 16 + g;
        const int r1 = r0 + 8;
#pragma unroll
        for (int nt = 0; nt < 8; nt++) {
            const int cb = n0 + wn * 64 + nt * 8 + tig * 2;
            float2 bA = *(const float2*)&e0[cb];
            float2 bB = *(const float2*)&e1[cb];
            const float* a = acc[mt][nt];
            float2 v0 = { a[0] + bA.x + bB.x, a[1] + bA.y + bB.y };
            float2 v1 = { a[2] + bA.x + bB.x, a[3] + bA.y + bB.y };
            *(float2*)&g_gates[(size_t)r0 * 4096 + cb] = v0;
            *(float2*)&g_gates[(size_t)r1 * 4096 + cb] = v1;
        }
    }
}

// ======================================================================
// tf32 mma.sync scores GEMM (unchanged, validated in R7):
// scores[b,s] += sum_n Walpha[n]*tanh(clip@Wctx^T + bctx + atth[b]) (atomic)
// M=65536, N=512, K=1024; BM=128, BN=256, BK=32.
// ======================================================================
__global__ void __launch_bounds__(512) mma_scores_kernel(
    const float* __restrict__ A0,
    const float* __restrict__ B01,
    const float* __restrict__ e0, const float* __restrict__ e1)
{
    constexpr int PITCH = 36;
    constexpr int AF = 128 * PITCH;
    constexpr int BF = 256 * PITCH;
    constexpr int STGF = AF + BF;

    extern __shared__ float smf[];
    const uint32_t smu = smem_u32(smf);

    const int tid = threadIdx.x;
    const int lane = tid & 31, w = tid >> 5;
    const int wm = w & 3, wn = w >> 2;
    const int g = lane >> 2, tig = lane & 3;
    const int m0 = blockIdx.y * 128, n0 = blockIdx.x * 256;

    float acc[2][8][4];
#pragma unroll
    for (int mt = 0; mt < 2; mt++)
#pragma unroll
        for (int nt = 0; nt < 8; nt++)
#pragma unroll
            for (int r = 0; r < 4; r++) acc[mt][nt][r] = 0.f;

    auto prefetch = [&](int t, int buf) {
        const int k0 = t * 32;
        const uint32_t abase = smu + (uint32_t)buf * STGF * 4;
        const uint32_t bbase = abase + AF * 4;
#pragma unroll
        for (int i = 0; i < 2; i++) {
            int q = tid + i * 512;
            int row = q >> 3, c4 = q & 7;
            CP_ASYNC16(abase + (uint32_t)(row * PITCH + c4 * 4) * 4,
                       (const void*)&A0[(size_t)(m0 + row) * 1024 + k0 + c4 * 4]);
        }
#pragma unroll
        for (int i = 0; i < 4; i++) {
            int q = tid + i * 512;
            int row = q >> 3, c4 = q & 7;
            CP_ASYNC16(bbase + (uint32_t)(row * PITCH + c4 * 4) * 4,
                       (const void*)&B01[(size_t)(n0 + row) * 1024 + k0 + c4 * 4]);
        }
        CP_COMMIT();
    };

    prefetch(0, 0);

    for (int t = 0; t < 32; t++) {
        const int buf = t & 1;
        if (t + 1 < 32) { prefetch(t + 1, buf ^ 1); CP_WAIT1(); }
        else            { CP_WAIT0(); }
        __syncthreads();

        const float* As = smf + buf * STGF;
        const float* Bs = As + AF;

#pragma unroll
        for (int s = 0; s < 4; s++) {
            uint32_t ah[2][4];
#pragma unroll
            for (int mt = 0; mt < 2; mt++) {
                const float* ap = As + (wm * 32 + mt * 16 + g) * PITCH + s * 8 + tig;
                ah[mt][0] = tf32_rna(ap[0]);
                ah[mt][1] = tf32_rna(ap[8 * PITCH]);
                ah[mt][2] = tf32_rna(ap[4]);
                ah[mt][3] = tf32_rna(ap[8 * PITCH + 4]);
            }
#pragma unroll
            for (int nt = 0; nt < 8; nt++) {
                const float* bp = Bs + (wn * 64 + nt * 8 + g) * PITCH + s * 8 + tig;
                uint32_t bh[2] = { tf32_rna(bp[0]), tf32_rna(bp[4]) };
#pragma unroll
                for (int mt = 0; mt < 2; mt++) mma8(acc[mt][nt], ah[mt], bh);
            }
        }
        __syncthreads();
    }

#pragma unroll
    for (int mt = 0; mt < 2; mt++) {
        const int r0 = m0 + wm * 32 + mt * 16 + g;
        const int r1 = r0 + 8;
        const int bb0 = r0 >> 6, bb1 = r1 >> 6;
        float s0 = 0.f, s1 = 0.f;
#pragma unroll
        for (int nt = 0; nt < 8; nt++) {
            const int cb = n0 + wn * 64 + nt * 8 + tig * 2;
            float2 bc = *(const float2*)&e0[cb];
            float2 wa = *(const float2*)&e1[cb];
            float2 a0 = *(const float2*)&g_atth[(size_t)bb0 * 512 + cb];
            float2 a1 = *(const float2*)&g_atth[(size_t)bb1 * 512 + cb];
            const float* a = acc[mt][nt];
            s0 += tanhf(a[0] + bc.x + a0.x) * wa.x + tanhf(a[1] + bc.y + a0.y) * wa.y;
            s1 += tanhf(a[2] + bc.x + a1.x) * wa.x + tanhf(a[3] + bc.y + a1.y) * wa.y;
        }
        s0 += __shfl_xor_sync(0xffffffffu, s0, 1);
        s0 += __shfl_xor_sync(0xffffffffu, s0, 2);
        s1 += __shfl_xor_sync(0xffffffffu, s1, 1);
        s1 += __shfl_xor_sync(0xffffffffu, s1, 2);
        if (tig == 0) {
            atomicAdd(&g_scores[r0], s0);
            atomicAdd(&g_scores[r1], s1);
        }
    }
}

// ======================================================================
// GEMM (small, SIMT): att_h += pre_h1 @ W_h2a^T  (split-K=4)
// ======================================================================
__global__ __launch_bounds__(256) void gemm_atth_kernel(
    const float* __restrict__ h1, const float* __restrict__ Wh2a)
{
    __shared__ __align__(16) float As[16][132];
    __shared__ __align__(16) float Ws[16][132];
    const int tid = threadIdx.x;
    const int tx = tid & 15, ty = tid >> 4;
    const int m0 = blockIdx.y * 128, n0 = blockIdx.x * 128;
    const int kbeg = blockIdx.z * 256, kend = kbeg + 256;

    float acc[8][8];
#pragma unroll
    for (int i = 0; i < 8; i++)
#pragma unroll
        for (int j = 0; j < 8; j++) acc[i][j] = 0.f;

    for (int k0 = kbeg; k0 < kend; k0 += 16) {
#pragma unroll
        for (int i = 0; i < 2; i++) {
            int lin = tid + i * 256;
            int row = lin >> 2, k4 = (lin & 3) << 2;
            float4 va = *(const float4*)&h1[(size_t)(m0 + row) * 1024 + k0 + k4];
            As[k4 + 0][row] = va.x; As[k4 + 1][row] = va.y;
            As[k4 + 2][row] = va.z; As[k4 + 3][row] = va.w;
            float4 vw = *(const float4*)&Wh2a[(size_t)(n0 + row) * 1024 + k0 + k4];
            Ws[k4 + 0][row] = vw.x; Ws[k4 + 1][row] = vw.y;
            Ws[k4 + 2][row] = vw.z; Ws[k4 + 3][row] = vw.w;
        }
        __syncthreads();
#pragma unroll
        for (int kk = 0; kk < 16; kk++) {
            float4 a0 = *(const float4*)&As[kk][4 * ty];
            float4 a1 = *(const float4*)&As[kk][64 + 4 * ty];
            float4 b0 = *(const float4*)&Ws[kk][4 * tx];
            float4 b1 = *(const float4*)&Ws[kk][64 + 4 * tx];
            float a[8] = {a0.x, a0.y, a0.z, a0.w, a1.x, a1.y, a1.z, a1.w};
            float b[8] = {b0.x, b0.y, b0.z, b0.w, b1.x, b1.y, b1.z, b1.w};
#pragma unroll
            for (int i = 0; i < 8; i++)
#pragma unroll
                for (int j = 0; j < 8; j++)
                    acc[i][j] = fmaf(a[i], b[j], acc[i][j]);
        }
        __syncthreads();
    }
#pragma unroll
    for (int i = 0; i < 8; i++) {
        int r = (i < 4) ? (4 * ty + i) : (64 + 4 * ty + i - 4);
#pragma unroll
        for (int j = 0; j < 8; j++) {
            int c = (j < 4) ? (4 * tx + j) : (64 + 4 * tx + j - 4);
            atomicAdd(&g_atth[(size_t)(m0 + r) * 512 + n0 + c], acc[i][j]);
        }
    }
}

// ======================================================================
// softmax over S=64 (mask + renorm) + weighted sum of clip -> g_attout
// ======================================================================
__global__ __launch_bounds__(256) void softmax_attout_kernel(
    const float* __restrict__ clip, const int* __restrict__ mask)
{
    const int b = blockIdx.x;
    const int tid = threadIdx.x;
    __shared__ float w[64];
    __shared__ float stat;

    if (tid < 64) w[tid] = g_scores[b * 64 + tid];
    __syncthreads();
    if (tid == 0) {
        float m = w[0];
        for (int s = 1; s < 64; s++) m = fmaxf(m, w[s]);
        stat = m;
    }
    __syncthreads();
    if (tid < 64) w[tid] = expf(w[tid] - stat);
    __syncthreads();
    if (tid == 0) {
        float s = 0.f;
        for (int i = 0; i < 64; i++) s += w[i];
        stat = s;
    }
    __syncthreads();
    if (tid < 64) w[tid] = (w[tid] / stat) * (float)mask[b * 64 + tid];
    __syncthreads();
    if (tid == 0) {
        float s = 0.f;
        for (int i = 0; i < 64; i++) s += w[i];
        stat = s;
    }
    __syncthreads();
    if (tid < 64) w[tid] = w[tid] / stat;
    __syncthreads();

    for (int d = tid; d < 1024; d += 256) {
        float acc = 0.f;
#pragma unroll 8
        for (int s = 0; s < 64; s++)
            acc += w[s] * clip[((size_t)b * 64 + s) * 1024 + d];
        g_attout[(size_t)b * 1024 + d] = acc;
    }
}

// ======================================================================
// LSTM pointwise
// ======================================================================
__global__ __launch_bounds__(256) void lstm_pointwise_kernel(
    const float* __restrict__ state_c, int stream, float* __restrict__ out)
{
    int idx = blockIdx.x * blockDim.x + threadIdx.x;
    int b = idx >> 10, j = idx & 1023;
    const float* g = g_gates + (size_t)b * 4096;
    float ig = 1.f / (1.f + expf(-g[j]));
    float fg = 1.f / (1.f + expf(-g[1024 + j]));
    float gg = tanhf(g[2048 + j]);
    float og = 1.f / (1.f + expf(-g[3072 + j]));
    float c_old = state_c[(size_t)stream * 1048576 + idx];
    float c_new = fg * c_old + ig * gg;
    float h_new = og * tanhf(c_new);
    out[(size_t)b * 2048 + stream * 1024 + j] = h_new;
    out[2097152 + (size_t)stream * 1048576 + idx] = h_new;
    out[4194304 + (size_t)stream * 1048576 + idx] = c_new;
}

// ======================================================================
extern "C" void kernel_launch(void* const* d_in, const int* in_sizes, int n_in,
                              void* d_out, int out_size)
{
    const float* xt       = (const float*)d_in[0];
    const float* event    = (const float*)d_in[2];
    const float* clip     = (const float*)d_in[3];
    const int*   clipmask = (const int*)  d_in[4];
    const float* state_h  = (const float*)d_in[5];
    const float* state_c  = (const float*)d_in[6];
    const float* W_ih0    = (const float*)d_in[7];
    const float* b_ih0    = (const float*)d_in[8];
    const float* W_hh0    = (const float*)d_in[9];
    const float* b_hh0    = (const float*)d_in[10];
    const float* W_ih1    = (const float*)d_in[11];
    const float* b_ih1    = (const float*)d_in[12];
    const float* W_hh1    = (const float*)d_in[13];
    const float* b_hh1    = (const float*)d_in[14];
    const float* W_ctx    = (const float*)d_in[15];
    const float* b_ctx    = (const float*)d_in[16];
    const float* W_h2a    = (const float*)d_in[17];
    const float* b_h2a    = (const float*)d_in[18];
    const float* W_alpha  = (const float*)d_in[19];
    const float* b_alpha  = (const float*)d_in[20];
    float* out = (float*)d_out;

    const float* h0 = state_h;
    const float* h1 = state_h + 1048576;

    const int SMEM_G = 3 * 49152;   // 147456 B (bf16 gates, 3 stages)
    const int SMEM_S = 2 * 55296;   // 110592 B (tf32 scores, 2 stages)
    cudaFuncSetAttribute(bf16_gates_kernel,
                         cudaFuncAttributeMaxDynamicSharedMemorySize, SMEM_G);
    cudaFuncSetAttribute(mma_scores_kernel,
                         cudaFuncAttributeMaxDynamicSharedMemorySize, SMEM_S);

    // ---- operand conversions (hi/lo bf16 splits) ----
    split_w_kernel<<<(4096 * 768 + 255) / 256, 256>>>(W_ih0, W_hh0, 0);
    split_w_kernel<<<(4096 * 768 + 255) / 256, 256>>>(W_ih1, W_hh1, 1);
    split_a_kernel<<<1024, 256>>>(xt,    0, 0, 0);
    split_a_kernel<<<1024, 256>>>(event, 0, 0, 1024);
    split_a_kernel<<<1024, 256>>>(h0,    0, 0, 2048);
    split_a_kernel<<<1024, 256>>>(xt,    0, 1, 0);
    split_a_kernel<<<1024, 256>>>(h1,    0, 1, 2048);

    // ---- attention pre-work ----
    init_atth_kernel<<<2048, 256>>>(b_h2a);
    init_scores_kernel<<<256, 256>>>(b_alpha);
    gemm_atth_kernel<<<dim3(4, 8, 4), 256>>>(h1, W_h2a);

    // ---- stream 0 LSTM ----
    bf16_gates_kernel<<<dim3(16, 8), 512, SMEM_G>>>(0, b_ih0, b_hh0);
    lstm_pointwise_kernel<<<4096, 256>>>(state_c, 0, out);

    // ---- attention scores + softmax + context ----
    mma_scores_kernel<<<dim3(2, 512), 512, SMEM_S>>>(clip, W_ctx, b_ctx, W_alpha);
    softmax_attout_kernel<<<1024, 256>>>(clip, clipmask);
    split_a_kernel<<<1024, 256>>>(nullptr, 1, 1, 1024);   // att -> A1 cols 1024..2047

    // ---- stream 1 LSTM ----
    bf16_gates_kernel<<<dim3(16, 8), 512, SMEM_G>>>(1, b_ih1, b_hh1);
    lstm_pointwise_kernel<<<4096, 256>>>(state_c, 1, out);
}